// round 1
// baseline (speedup 1.0000x reference)
#include <cuda_runtime.h>

#define HH 600
#define WW 600
#define HWX (HH*WW)
#define C 64
#define E 256
#define NL 7
#define CROPV 50
#define NOUT 500
#define NTRI ((NOUT*(NOUT+1))/2)   // 125250
#define MAXBIN 100

// ---- scratch (static device arrays; no runtime allocation) ----
__device__ float g_bufA[C * HWX];          // 92.16 MB
__device__ float g_bufB[C * HWX];          // 92.16 MB
__device__ float g_u[HH * C];              // W_in @ x  (no bias)
__device__ float g_dproj[(MAXBIN + 1) * C];// W_in @ dist_table + b_in
__device__ float g_wf[NL * 49 * C * C];    // folded weights, layout [l][tap][ci][co]
__device__ float g_bf[NL * C];             // folded biases

// ------------------------------------------------------------------
// prep: u[i][c] = sum_e w_in[c,e] * x[i,e]
__global__ void prep_u(const float* __restrict__ x, const float* __restrict__ w_in) {
    int i = blockIdx.x, c = threadIdx.x;
    const float* xr = x + i * E;
    const float* wr = w_in + c * E;
    float s = 0.f;
    #pragma unroll 8
    for (int e = 0; e < E; e++) s += wr[e] * xr[e];
    g_u[i * C + c] = s;
}

// prep: dproj[p][c] = b_in[c] + sum_e w_in[c,e] * dist_table[p,e]
__global__ void prep_dproj(const float* __restrict__ dist, const float* __restrict__ w_in,
                           const float* __restrict__ b_in) {
    int p = blockIdx.x, c = threadIdx.x;
    const float* dr = dist + p * E;
    const float* wr = w_in + c * E;
    float s = b_in[c];
    #pragma unroll 8
    for (int e = 0; e < E; e++) s += wr[e] * dr[e];
    g_dproj[p * C + c] = s;
}

// prep: fold BN scale into conv weights, relayout to [l][tap][ci][co]
__global__ void prep_fold(const float* __restrict__ w_dil, const float* __restrict__ gamma,
                          const float* __restrict__ var) {
    int blk = blockIdx.x;          // 0 .. NL*49-1
    int l = blk / 49, tap = blk % 49;
    int tid = threadIdx.x;
    float* dstp = g_wf + (l * 49 + tap) * C * C;
    const float* wsrc = w_dil + l * C * C * 49;
    #pragma unroll
    for (int k = 0; k < 16; k++) {
        int idx = tid * 16 + k;        // idx = ci*64 + co
        int co = idx & 63, ci = idx >> 6;
        float s = gamma[l * C + co] * rsqrtf(var[l * C + co] + 1e-5f);
        dstp[idx] = wsrc[(co * C + ci) * 49 + tap] * s;
    }
}

// prep: folded bias = (b - mean) * s + beta
__global__ void prep_bias(const float* __restrict__ b_dil, const float* __restrict__ gamma,
                          const float* __restrict__ beta, const float* __restrict__ mean,
                          const float* __restrict__ var) {
    int l = blockIdx.x, c = threadIdx.x;
    float s = gamma[l * C + c] * rsqrtf(var[l * C + c] + 1e-5f);
    g_bf[l * C + c] = (b_dil[l * C + c] - mean[l * C + c]) * s + beta[l * C + c];
}

// ------------------------------------------------------------------
// pair + input 1x1 conv:   bufA[c,i,j] = b_in + W@pair
// = cross(i,j,c) + 0.5*(u_i[c]+u_j[c]) + dproj[pos(i,j)][c]
// cross via GEMM over embed dim.
__global__ void pair_gemm(const float* __restrict__ x, const float* __restrict__ w_in) {
    __shared__ float Ae[32 * 68];
    __shared__ float Be[32 * 68];
    __shared__ float xi[E];
    int i = blockIdx.y;
    int j0 = blockIdx.x * 64;
    int tid = threadIdx.x;
    xi[tid] = x[i * E + tid];
    __syncthreads();

    int ty = tid >> 4, tx = tid & 15;
    int c0 = ty * 4, p0 = tx * 4;
    int srow = tid >> 2;           // staging: 0..63
    int eb = (tid & 3) * 8;        // staging: embed sub-base
    bool jok = (j0 + srow) < WW;
    const float* xrow = x + (j0 + srow) * E;

    float acc[4][4] = {};
    #pragma unroll 1
    for (int e0 = 0; e0 < E; e0 += 32) {
        // Ae[e][c] = w_in[c,e0+e] * xi[e0+e]   (c = srow here)
        {
            const float* wr = w_in + srow * E + e0 + eb;
            #pragma unroll
            for (int k = 0; k < 8; k++) Ae[(eb + k) * 68 + srow] = wr[k] * xi[e0 + eb + k];
        }
        // Be[e][j] = x[j0+j, e0+e]
        if (jok) {
            #pragma unroll
            for (int k = 0; k < 8; k++) Be[(eb + k) * 68 + srow] = xrow[e0 + eb + k];
        } else {
            #pragma unroll
            for (int k = 0; k < 8; k++) Be[(eb + k) * 68 + srow] = 0.f;
        }
        __syncthreads();
        #pragma unroll
        for (int e = 0; e < 32; e++) {
            float4 a4 = *(const float4*)(Ae + e * 68 + c0);
            float4 b4 = *(const float4*)(Be + e * 68 + p0);
            float av[4] = {a4.x, a4.y, a4.z, a4.w};
            float bv[4] = {b4.x, b4.y, b4.z, b4.w};
            #pragma unroll
            for (int aa = 0; aa < 4; aa++)
                #pragma unroll
                for (int bb = 0; bb < 4; bb++)
                    acc[aa][bb] = fmaf(av[aa], bv[bb], acc[aa][bb]);
        }
        __syncthreads();
    }

    #pragma unroll
    for (int aa = 0; aa < 4; aa++) {
        int c = c0 + aa;
        float uic = g_u[i * C + c];
        #pragma unroll
        for (int bb = 0; bb < 4; bb++) {
            int j = j0 + p0 + bb;
            if (j < WW) {
                int pos = (i > j) ? (i - j) : (j - i);
                if (pos > MAXBIN) pos = MAXBIN;
                float v = acc[aa][bb] + 0.5f * (uic + g_u[j * C + c]) + g_dproj[pos * C + c];
                g_bufA[c * HWX + i * WW + j] = v;
            }
        }
    }
}

// ------------------------------------------------------------------
// dilated 7x7 conv + folded BN + residual + relu.
// layer l: src = (l even ? A : B), dst = other. dil = 1<<l.
__global__ void conv_dil(int l) {
    __shared__ float Wt[64 * 68];
    __shared__ float It[64 * 68];
    const float* src = (l & 1) ? g_bufB : g_bufA;
    float* dst       = (l & 1) ? g_bufA : g_bufB;
    const float* wt  = g_wf + l * 49 * C * C;
    const float* bias = g_bf + l * C;
    int dil = 1 << l;

    int y = blockIdx.y;
    int x0 = blockIdx.x * 64;
    int tid = threadIdx.x;
    int ty = tid >> 4, tx = tid & 15;
    int c0 = ty * 4, p0 = tx * 4;
    int sci = tid >> 2;          // staging row (ci) 0..63
    int sb = (tid & 3) * 16;     // staging col base

    float acc[4][4] = {};
    #pragma unroll 1
    for (int tap = 0; tap < 49; tap++) {
        int ky = tap / 7, kx = tap - ky * 7;
        int yy = y + (ky - 3) * dil;
        int xs = x0 + (kx - 3) * dil;
        // stage weights (contiguous [ci][co] block of 4096 floats)
        {
            const float4* wsrc = (const float4*)(wt + tap * 4096 + tid * 16);
            float4* wdst = (float4*)(Wt + sci * 68 + sb);
            #pragma unroll
            for (int q = 0; q < 4; q++) wdst[q] = wsrc[q];
        }
        // stage shifted input row segment
        {
            float4* idst = (float4*)(It + sci * 68 + sb);
            if (yy < 0 || yy >= HH) {
                float4 z = make_float4(0.f, 0.f, 0.f, 0.f);
                #pragma unroll
                for (int q = 0; q < 4; q++) idst[q] = z;
            } else {
                const float* row = src + sci * HWX + yy * WW;
                int gx0 = xs + sb;
                if (gx0 >= 0 && gx0 + 15 < WW && ((gx0 & 3) == 0)) {
                    const float4* rs = (const float4*)(row + gx0);
                    #pragma unroll
                    for (int q = 0; q < 4; q++) idst[q] = rs[q];
                } else {
                    #pragma unroll
                    for (int k = 0; k < 16; k++) {
                        int gx = gx0 + k;
                        It[sci * 68 + sb + k] = (gx >= 0 && gx < WW) ? row[gx] : 0.f;
                    }
                }
            }
        }
        __syncthreads();
        #pragma unroll 8
        for (int ci = 0; ci < 64; ci++) {
            float4 a4 = *(const float4*)(Wt + ci * 68 + c0);
            float4 b4 = *(const float4*)(It + ci * 68 + p0);
            float av[4] = {a4.x, a4.y, a4.z, a4.w};
            float bv[4] = {b4.x, b4.y, b4.z, b4.w};
            #pragma unroll
            for (int aa = 0; aa < 4; aa++)
                #pragma unroll
                for (int bb = 0; bb < 4; bb++)
                    acc[aa][bb] = fmaf(av[aa], bv[bb], acc[aa][bb]);
        }
        __syncthreads();
    }

    #pragma unroll
    for (int aa = 0; aa < 4; aa++) {
        int c = c0 + aa;
        float bb_ = bias[c];
        #pragma unroll
        for (int bb = 0; bb < 4; bb++) {
            int xg = x0 + p0 + bb;
            if (xg < WW) {
                int off = c * HWX + y * WW + xg;
                float v = acc[aa][bb] + bb_ + src[off];
                dst[off] = fmaxf(v, 0.f);
            }
        }
    }
}

// ------------------------------------------------------------------
// output 1x1 conv: reads bufB (after 7 layers), writes bufA. No relu/residual.
__global__ void conv_out(const float* __restrict__ w_out, const float* __restrict__ b_out) {
    __shared__ float Wt[64 * 68];
    __shared__ float It[64 * 68];
    const float* src = g_bufB;
    float* dst = g_bufA;
    int y = blockIdx.y;
    int x0 = blockIdx.x * 64;
    int tid = threadIdx.x;
    int ty = tid >> 4, tx = tid & 15;
    int c0 = ty * 4, p0 = tx * 4;

    // stage transposed weights: Wt[ci][co] = w_out[co][ci]
    {
        int co = tid >> 2, cib = (tid & 3) * 16;
        #pragma unroll
        for (int k = 0; k < 16; k++) Wt[(cib + k) * 68 + co] = w_out[co * 64 + cib + k];
    }
    // stage input
    {
        int sci = tid >> 2, sb = (tid & 3) * 16;
        const float* row = src + sci * HWX + y * WW + x0;
        #pragma unroll
        for (int k = 0; k < 16; k++) {
            int gx = x0 + sb + k;
            It[sci * 68 + sb + k] = (gx < WW) ? row[sb + k] : 0.f;
        }
    }
    __syncthreads();
    float acc[4][4] = {};
    #pragma unroll 8
    for (int ci = 0; ci < 64; ci++) {
        float4 a4 = *(const float4*)(Wt + ci * 68 + c0);
        float4 b4 = *(const float4*)(It + ci * 68 + p0);
        float av[4] = {a4.x, a4.y, a4.z, a4.w};
        float bv[4] = {b4.x, b4.y, b4.z, b4.w};
        #pragma unroll
        for (int aa = 0; aa < 4; aa++)
            #pragma unroll
            for (int bb = 0; bb < 4; bb++)
                acc[aa][bb] = fmaf(av[aa], bv[bb], acc[aa][bb]);
    }
    #pragma unroll
    for (int aa = 0; aa < 4; aa++) {
        int c = c0 + aa;
        float bb_ = b_out[c];
        #pragma unroll
        for (int bb = 0; bb < 4; bb++) {
            int xg = x0 + p0 + bb;
            if (xg < WW)
                dst[c * HWX + y * WW + xg] = acc[aa][bb] + bb_;
        }
    }
}

// ------------------------------------------------------------------
__device__ __forceinline__ int tri_offs(int r) { return r * NOUT - (r * (r - 1)) / 2; }

__global__ void head_k(const float* __restrict__ w_head, const float* __restrict__ b_head,
                       float* __restrict__ out) {
    int k = blockIdx.x * blockDim.x + threadIdx.x;
    if (k >= NTRI) return;
    const float* h = g_bufA;
    // invert triu row index
    float disc = (2.f * NOUT + 1.f) * (2.f * NOUT + 1.f) - 8.f * (float)k;
    int r = (int)(((2.f * NOUT + 1.f) - sqrtf(disc)) * 0.5f);
    if (r < 0) r = 0;
    if (r > NOUT - 1) r = NOUT - 1;
    while (r > 0 && tri_offs(r) > k) r--;
    while (r < NOUT - 1 && tri_offs(r + 1) <= k) r++;
    int c = r + (k - tri_offs(r));
    int yy = CROPV + r, xx = CROPV + c;

    float s = b_head[0];
    const float* p = h + yy * WW + xx;
    #pragma unroll
    for (int ci = 0; ci < C; ci++) s += p[ci * HWX] * __ldg(&w_head[ci]);
    out[k] = s;
}

// ------------------------------------------------------------------
extern "C" void kernel_launch(void* const* d_in, const int* in_sizes, int n_in,
                              void* d_out, int out_size) {
    const float* x      = (const float*)d_in[0];
    const float* dist   = (const float*)d_in[1];
    const float* w_in   = (const float*)d_in[2];
    const float* b_in   = (const float*)d_in[3];
    const float* w_dil  = (const float*)d_in[4];
    const float* b_dil  = (const float*)d_in[5];
    const float* gamma  = (const float*)d_in[6];
    const float* beta   = (const float*)d_in[7];
    const float* mean   = (const float*)d_in[8];
    const float* var    = (const float*)d_in[9];
    const float* w_out  = (const float*)d_in[10];
    const float* b_out  = (const float*)d_in[11];
    const float* w_head = (const float*)d_in[12];
    const float* b_head = (const float*)d_in[13];
    float* out = (float*)d_out;

    prep_u<<<HH, C>>>(x, w_in);
    prep_dproj<<<MAXBIN + 1, C>>>(dist, w_in, b_in);
    prep_fold<<<NL * 49, 256>>>(w_dil, gamma, var);
    prep_bias<<<NL, C>>>(b_dil, gamma, beta, mean, var);

    dim3 grid((WW + 63) / 64, HH);
    pair_gemm<<<grid, 256>>>(x, w_in);

    for (int l = 0; l < NL; l++)
        conv_dil<<<grid, 256>>>(l);

    conv_out<<<grid, 256>>>(w_out, b_out);

    head_k<<<(NTRI + 255) / 256, 256>>>(w_head, b_head, out);
}

// round 4
// speedup vs baseline: 3.5610x; 3.5610x over previous
#include <cuda_runtime.h>
#include <cuda_bf16.h>
#include <cstdint>
#include <cstddef>

#define HH 600
#define WW 600
#define HWX (HH*WW)
#define C 64
#define E 256
#define NL 7
#define CROPV 50
#define NOUT 500
#define NTRI ((NOUT*(NOUT+1))/2)   // 125250
#define MAXBIN 100

__device__ __forceinline__ uint32_t smem_to_u32(const void* p) {
    uint32_t a;
    asm("{ .reg .u64 t; cvta.to.shared.u64 t, %1; cvt.u32.u64 %0, t; }" : "=r"(a) : "l"(p));
    return a;
}
__device__ __forceinline__ float bf2f(uint32_t u) {
    return __bfloat162float(__ushort_as_bfloat16((unsigned short)u));
}
__device__ __forceinline__ unsigned short f2bfu(float v) {
    return __bfloat16_as_ushort(__float2bfloat16_rn(v));
}

#define LDSM_X4(r0, r1, r2, r3, a) \
    asm volatile("ldmatrix.sync.aligned.m8n8.x4.shared.b16 {%0,%1,%2,%3}, [%4];" \
        : "=r"(r0), "=r"(r1), "=r"(r2), "=r"(r3) : "r"(a))
#define LDSM_X4_T(r0, r1, r2, r3, a) \
    asm volatile("ldmatrix.sync.aligned.m8n8.x4.trans.shared.b16 {%0,%1,%2,%3}, [%4];" \
        : "=r"(r0), "=r"(r1), "=r"(r2), "=r"(r3) : "r"(a))

__device__ __forceinline__ void mma16816(float* d, const uint32_t* a, uint32_t b0, uint32_t b1) {
    asm volatile("mma.sync.aligned.m16n8k16.row.col.f32.bf16.bf16.f32 "
        "{%0,%1,%2,%3}, {%4,%5,%6,%7}, {%8,%9}, {%0,%1,%2,%3};"
        : "+f"(d[0]), "+f"(d[1]), "+f"(d[2]), "+f"(d[3])
        : "r"(a[0]), "r"(a[1]), "r"(a[2]), "r"(a[3]), "r"(b0), "r"(b1));
}

// ---------------- device buffers ----------------
__device__ __nv_bfloat16 g_Ahi[(size_t)HWX * C];
__device__ __nv_bfloat16 g_Alo[(size_t)HWX * C];
__device__ __nv_bfloat16 g_Bhi[(size_t)HWX * C];
__device__ __nv_bfloat16 g_Blo[(size_t)HWX * C];
__device__ __nv_bfloat16 g_whi[NL * 49 * C * C];   // [l][tap][ci][co]
__device__ __nv_bfloat16 g_wlo[NL * 49 * C * C];
__device__ float g_bf[NL * C];
__device__ float g_u[HH * C];
__device__ float g_dproj[(MAXBIN + 1) * C];
__device__ float g_weff[C + 1];

// ---------------- prep kernels ----------------
__global__ void prep_u(const float* __restrict__ x, const float* __restrict__ w_in) {
    int i = blockIdx.x, c = threadIdx.x;
    const float* xr = x + i * E;
    const float* wr = w_in + c * E;
    float s = 0.f;
    #pragma unroll 8
    for (int e = 0; e < E; e++) s += wr[e] * xr[e];
    g_u[i * C + c] = s;
}

__global__ void prep_dproj(const float* __restrict__ dist, const float* __restrict__ w_in,
                           const float* __restrict__ b_in) {
    int p = blockIdx.x, c = threadIdx.x;
    const float* dr = dist + p * E;
    const float* wr = w_in + c * E;
    float s = b_in[c];
    #pragma unroll 8
    for (int e = 0; e < E; e++) s += wr[e] * dr[e];
    g_dproj[p * C + c] = s;
}

// fold BN into weights, relayout [l][tap][ci][co], split bf16 hi/lo
__global__ void prep_fold(const float* __restrict__ w_dil, const float* __restrict__ gamma,
                          const float* __restrict__ var) {
    int blk = blockIdx.x;                 // l*49 + tap
    int l = blk / 49, tap = blk % 49;
    int tid = threadIdx.x;
    __nv_bfloat16* dh = g_whi + blk * 4096;
    __nv_bfloat16* dl = g_wlo + blk * 4096;
    const float* wsrc = w_dil + l * C * C * 49;
    #pragma unroll
    for (int k = 0; k < 16; k++) {
        int idx = tid * 16 + k;           // ci*64 + co
        int ci = idx >> 6, co = idx & 63;
        float s = gamma[l * C + co] * rsqrtf(var[l * C + co] + 1e-5f);
        float v = wsrc[(co * C + ci) * 49 + tap] * s;
        unsigned short h = f2bfu(v);
        dh[idx] = __ushort_as_bfloat16(h);
        dl[idx] = __float2bfloat16_rn(v - bf2f(h));
    }
}

__global__ void prep_bias(const float* __restrict__ b_dil, const float* __restrict__ gamma,
                          const float* __restrict__ beta, const float* __restrict__ mean,
                          const float* __restrict__ var) {
    int l = blockIdx.x, c = threadIdx.x;
    float s = gamma[l * C + c] * rsqrtf(var[l * C + c] + 1e-5f);
    g_bf[l * C + c] = (b_dil[l * C + c] - mean[l * C + c]) * s + beta[l * C + c];
}

__global__ void prep_weff(const float* __restrict__ w_out, const float* __restrict__ b_out,
                          const float* __restrict__ w_head, const float* __restrict__ b_head) {
    int ci = threadIdx.x;
    float s = 0.f;
    for (int co = 0; co < C; co++) s += w_head[co] * w_out[co * C + ci];
    g_weff[ci] = s;
    if (ci == 0) {
        float b = b_head[0];
        for (int co = 0; co < C; co++) b += w_head[co] * b_out[co];
        g_weff[C] = b;
    }
}

// ---------------- pair + input 1x1 conv (fp32 FFMA), writes NHWC bf16 hi/lo ----------------
__global__ void pair_gemm(const float* __restrict__ x, const float* __restrict__ w_in) {
    __shared__ float Ae[32 * 68];
    __shared__ float Be[32 * 68];
    __shared__ float xi[E];
    int i = blockIdx.y;
    int j0 = blockIdx.x * 64;
    int tid = threadIdx.x;
    xi[tid] = x[i * E + tid];
    __syncthreads();

    int ty = tid >> 4, tx = tid & 15;
    int c0 = ty * 4, p0 = tx * 4;
    int srow = tid >> 2;
    int eb = (tid & 3) * 8;
    bool jok = (j0 + srow) < WW;
    const float* xrow = x + (j0 + srow) * E;

    float acc[4][4] = {};
    #pragma unroll 1
    for (int e0 = 0; e0 < E; e0 += 32) {
        {
            const float* wr = w_in + srow * E + e0 + eb;
            #pragma unroll
            for (int k = 0; k < 8; k++) Ae[(eb + k) * 68 + srow] = wr[k] * xi[e0 + eb + k];
        }
        if (jok) {
            #pragma unroll
            for (int k = 0; k < 8; k++) Be[(eb + k) * 68 + srow] = xrow[e0 + eb + k];
        } else {
            #pragma unroll
            for (int k = 0; k < 8; k++) Be[(eb + k) * 68 + srow] = 0.f;
        }
        __syncthreads();
        #pragma unroll
        for (int e = 0; e < 32; e++) {
            float4 a4 = *(const float4*)(Ae + e * 68 + c0);
            float4 b4 = *(const float4*)(Be + e * 68 + p0);
            float av[4] = {a4.x, a4.y, a4.z, a4.w};
            float bv[4] = {b4.x, b4.y, b4.z, b4.w};
            #pragma unroll
            for (int aa = 0; aa < 4; aa++)
                #pragma unroll
                for (int bb = 0; bb < 4; bb++)
                    acc[aa][bb] = fmaf(av[aa], bv[bb], acc[aa][bb]);
        }
        __syncthreads();
    }

    #pragma unroll
    for (int bb = 0; bb < 4; bb++) {
        int j = j0 + p0 + bb;
        if (j < WW) {
            int pos = (i > j) ? (i - j) : (j - i);
            if (pos > MAXBIN) pos = MAXBIN;
            uint32_t hw[2], lw[2];
            #pragma unroll
            for (int g = 0; g < 2; g++) {
                uint32_t h2 = 0, l2 = 0;
                #pragma unroll
                for (int e = 0; e < 2; e++) {
                    int aa = g * 2 + e;
                    int c = c0 + aa;
                    float v = acc[aa][bb] + 0.5f * (g_u[i * C + c] + g_u[j * C + c]) + g_dproj[pos * C + c];
                    unsigned short h = f2bfu(v);
                    unsigned short lo = f2bfu(v - bf2f(h));
                    h2 |= ((uint32_t)h) << (16 * e);
                    l2 |= ((uint32_t)lo) << (16 * e);
                }
                hw[g] = h2; lw[g] = l2;
            }
            size_t off = ((size_t)i * WW + j) * C + c0;
            *(uint2*)(g_Ahi + off) = make_uint2(hw[0], hw[1]);
            *(uint2*)(g_Alo + off) = make_uint2(lw[0], lw[1]);
        }
    }
}

// ---------------- dilated conv via mma.sync bf16 hi/lo (3-pass), NHWC ----------------
// smem: bias(256) | Ahi 16K | Alo 16K | Whi 8K | Wlo 8K = 49408 B
#define OFF_BIAS 0
#define OFF_AH   256
#define OFF_AL   (256 + 16384)
#define OFF_WH   (256 + 32768)
#define OFF_WL   (256 + 40960)
#define SMEM_CONV 49408

__global__ __launch_bounds__(256, 2) void conv_mma(int l) {
    extern __shared__ char smem[];
    const uint32_t sb = smem_to_u32(smem);
    const int tid = threadIdx.x;
    const int wid = tid >> 5, lane = tid & 31;
    const int dil = 1 << l;
    const int y = blockIdx.y;
    const int x0 = blockIdx.x * 128;

    const __nv_bfloat16* __restrict__ shi = (l & 1) ? g_Bhi : g_Ahi;
    const __nv_bfloat16* __restrict__ slo = (l & 1) ? g_Blo : g_Alo;
    __nv_bfloat16* __restrict__ dhi = (l & 1) ? g_Ahi : g_Bhi;
    __nv_bfloat16* __restrict__ dlo = (l & 1) ? g_Alo : g_Blo;
    const __nv_bfloat16* __restrict__ wh = g_whi + l * 49 * 4096;
    const __nv_bfloat16* __restrict__ wl = g_wlo + l * 49 * 4096;

    if (tid < C) ((float*)(smem + OFF_BIAS))[tid] = g_bf[l * C + tid];

    // staging maps
    int aRow[4], aC[4]; uint32_t aOff[4];
    #pragma unroll
    for (int k = 0; k < 4; k++) {
        int chunk = tid + k * 256;       // 0..1023 = row*8 + cchunk
        aRow[k] = chunk >> 3;
        int cc = chunk & 7;
        aC[k] = cc * 8;
        aOff[k] = (uint32_t)(aRow[k] * 128 + ((cc ^ (aRow[k] & 7)) << 4));
    }
    int wCi[2], wC[2]; uint32_t wOff[2];
    #pragma unroll
    for (int k = 0; k < 2; k++) {
        int chunk = tid + k * 256;       // 0..511 = ci*8 + cchunk
        wCi[k] = chunk >> 3;
        int cc = chunk & 7;
        wC[k] = cc * 8;
        wOff[k] = (uint32_t)(wCi[k] * 128 + ((cc ^ (wCi[k] & 7)) << 4));
    }

    // ldmatrix address components
    const int row0 = wid * 16;
    const int quad = lane >> 3;
    const int rA = row0 + (lane & 7) + ((quad & 1) << 3);   // A frag row
    const int aChunkAdd = quad >> 1;                         // + 2*ks
    const int rBbase = (lane & 7) + (((lane >> 3) & 1) << 3); // + 16*ks
    const int bChunkAdd = lane >> 4;                          // + 2*p

    float acc[8][4] = {};

    #pragma unroll 1
    for (int tap = 0; tap < 49; ++tap) {
        int dy = tap / 7 - 3, dx = tap % 7 - 3;
        int yy = y + dy * dil;
        bool yok = (yy >= 0) && (yy < HH);
        int xs = x0 + dx * dil;

        // stage A hi/lo
        #pragma unroll
        for (int k = 0; k < 4; k++) {
            int xx = xs + aRow[k];
            bool ok = yok && (xx >= 0) && (xx < WW);
            uint4 vh = make_uint4(0, 0, 0, 0), vl = make_uint4(0, 0, 0, 0);
            if (ok) {
                size_t g = ((size_t)yy * WW + xx) * C + aC[k];
                vh = *(const uint4*)(shi + g);
                vl = *(const uint4*)(slo + g);
            }
            *(uint4*)(smem + OFF_AH + aOff[k]) = vh;
            *(uint4*)(smem + OFF_AL + aOff[k]) = vl;
        }
        // stage W hi/lo
        {
            const __nv_bfloat16* wph = wh + tap * 4096;
            const __nv_bfloat16* wpl = wl + tap * 4096;
            #pragma unroll
            for (int k = 0; k < 2; k++) {
                *(uint4*)(smem + OFF_WH + wOff[k]) = *(const uint4*)(wph + wCi[k] * 64 + wC[k]);
                *(uint4*)(smem + OFF_WL + wOff[k]) = *(const uint4*)(wpl + wCi[k] * 64 + wC[k]);
            }
        }
        __syncthreads();

        #pragma unroll
        for (int ks = 0; ks < 4; ks++) {
            uint32_t ah[4], al[4];
            {
                int chunk = 2 * ks + aChunkAdd;
                uint32_t ao = (uint32_t)(rA * 128 + ((chunk ^ (rA & 7)) << 4));
                LDSM_X4(ah[0], ah[1], ah[2], ah[3], sb + OFF_AH + ao);
                LDSM_X4(al[0], al[1], al[2], al[3], sb + OFF_AL + ao);
            }
            int rB = rBbase + 16 * ks;
            #pragma unroll
            for (int p = 0; p < 4; p++) {
                int chunk = 2 * p + bChunkAdd;
                uint32_t bo = (uint32_t)(rB * 128 + ((chunk ^ (rB & 7)) << 4));
                uint32_t b0, b1, b2, b3;
                LDSM_X4_T(b0, b1, b2, b3, sb + OFF_WH + bo);
                mma16816(acc[2 * p],     ah, b0, b1);
                mma16816(acc[2 * p + 1], ah, b2, b3);
                mma16816(acc[2 * p],     al, b0, b1);
                mma16816(acc[2 * p + 1], al, b2, b3);
                LDSM_X4_T(b0, b1, b2, b3, sb + OFF_WL + bo);
                mma16816(acc[2 * p],     ah, b0, b1);
                mma16816(acc[2 * p + 1], ah, b2, b3);
            }
        }
        __syncthreads();
    }

    // epilogue: + bias + residual(hi+lo), relu, re-split, store
    const float* sbias = (const float*)(smem + OFF_BIAS);
    int rtop = row0 + (lane >> 2);
    int cpair = (lane & 3) * 2;
    #pragma unroll
    for (int half = 0; half < 2; half++) {
        int xg = x0 + rtop + half * 8;
        if (xg < WW) {
            size_t prow = ((size_t)y * WW + xg) * C;
            #pragma unroll
            for (int nt = 0; nt < 8; nt++) {
                int col = nt * 8 + cpair;
                size_t p = prow + col;
                uint32_t rh = *(const uint32_t*)(shi + p);
                uint32_t rl = *(const uint32_t*)(slo + p);
                float v0 = acc[nt][half * 2]     + sbias[col]     + bf2f(rh & 0xffffu) + bf2f(rl & 0xffffu);
                float v1 = acc[nt][half * 2 + 1] + sbias[col + 1] + bf2f(rh >> 16)     + bf2f(rl >> 16);
                v0 = fmaxf(v0, 0.f); v1 = fmaxf(v1, 0.f);
                unsigned short h0 = f2bfu(v0), h1 = f2bfu(v1);
                unsigned short l0 = f2bfu(v0 - bf2f(h0)), l1 = f2bfu(v1 - bf2f(h1));
                *(uint32_t*)(dhi + p) = (uint32_t)h0 | ((uint32_t)h1 << 16);
                *(uint32_t*)(dlo + p) = (uint32_t)l0 | ((uint32_t)l1 << 16);
            }
        }
    }
}

// ---------------- head (conv_out folded into w_eff) ----------------
__device__ __forceinline__ int tri_offs(int r) { return r * NOUT - (r * (r - 1)) / 2; }

__global__ void head_k(float* __restrict__ out) {
    int k = blockIdx.x * blockDim.x + threadIdx.x;
    if (k >= NTRI) return;
    float disc = (2.f * NOUT + 1.f) * (2.f * NOUT + 1.f) - 8.f * (float)k;
    int r = (int)(((2.f * NOUT + 1.f) - sqrtf(disc)) * 0.5f);
    if (r < 0) r = 0;
    if (r > NOUT - 1) r = NOUT - 1;
    while (r > 0 && tri_offs(r) > k) r--;
    while (r < NOUT - 1 && tri_offs(r + 1) <= k) r++;
    int c = r + (k - tri_offs(r));
    int yy = CROPV + r, xx = CROPV + c;
    size_t p = ((size_t)yy * WW + xx) * C;

    float s = g_weff[C];
    const uint4* rh = (const uint4*)(g_Bhi + p);
    const uint4* rl = (const uint4*)(g_Blo + p);
    #pragma unroll
    for (int q = 0; q < 8; q++) {
        uint4 vh = rh[q], vl = rl[q];
        uint32_t vhw[4] = {vh.x, vh.y, vh.z, vh.w};
        uint32_t vlw[4] = {vl.x, vl.y, vl.z, vl.w};
        #pragma unroll
        for (int e = 0; e < 4; e++) {
            int ci = q * 8 + e * 2;
            float h0 = bf2f(vhw[e] & 0xffffu) + bf2f(vlw[e] & 0xffffu);
            float h1 = bf2f(vhw[e] >> 16) + bf2f(vlw[e] >> 16);
            s = fmaf(h0, __ldg(&g_weff[ci]), s);
            s = fmaf(h1, __ldg(&g_weff[ci + 1]), s);
        }
    }
    out[k] = s;
}

// ------------------------------------------------------------------
extern "C" void kernel_launch(void* const* d_in, const int* in_sizes, int n_in,
                              void* d_out, int out_size) {
    const float* x      = (const float*)d_in[0];
    const float* dist   = (const float*)d_in[1];
    const float* w_in   = (const float*)d_in[2];
    const float* b_in   = (const float*)d_in[3];
    const float* w_dil  = (const float*)d_in[4];
    const float* b_dil  = (const float*)d_in[5];
    const float* gamma  = (const float*)d_in[6];
    const float* beta   = (const float*)d_in[7];
    const float* mean   = (const float*)d_in[8];
    const float* var    = (const float*)d_in[9];
    const float* w_out  = (const float*)d_in[10];
    const float* b_out  = (const float*)d_in[11];
    const float* w_head = (const float*)d_in[12];
    const float* b_head = (const float*)d_in[13];
    float* out = (float*)d_out;

    cudaFuncSetAttribute(conv_mma, cudaFuncAttributeMaxDynamicSharedMemorySize, SMEM_CONV);

    prep_u<<<HH, C>>>(x, w_in);
    prep_dproj<<<MAXBIN + 1, C>>>(dist, w_in, b_in);
    prep_fold<<<NL * 49, 256>>>(w_dil, gamma, var);
    prep_bias<<<NL, C>>>(b_dil, gamma, beta, mean, var);
    prep_weff<<<1, C>>>(w_out, b_out, w_head, b_head);

    pair_gemm<<<dim3((WW + 63) / 64, HH), 256>>>(x, w_in);

    for (int l = 0; l < NL; l++)
        conv_mma<<<dim3((WW + 127) / 128, HH), 256, SMEM_CONV>>>(l);

    head_k<<<(NTRI + 255) / 256, 256>>>(out);
}

// round 5
// speedup vs baseline: 4.5449x; 1.2763x over previous
#include <cuda_runtime.h>
#include <cuda_bf16.h>
#include <cstdint>
#include <cstddef>

#define HH 600
#define WW 600
#define HWX (HH*WW)
#define C 64
#define E 256
#define NL 7
#define CROPV 50
#define NOUT 500
#define NTRI ((NOUT*(NOUT+1))/2)   // 125250
#define MAXBIN 100

__device__ __forceinline__ uint32_t smem_to_u32(const void* p) {
    uint32_t a;
    asm("{ .reg .u64 t; cvta.to.shared.u64 t, %1; cvt.u32.u64 %0, t; }" : "=r"(a) : "l"(p));
    return a;
}
__device__ __forceinline__ float bf2f(uint32_t u) {
    return __bfloat162float(__ushort_as_bfloat16((unsigned short)u));
}
__device__ __forceinline__ unsigned short f2bfu(float v) {
    return __bfloat16_as_ushort(__float2bfloat16_rn(v));
}

#define LDSM_X4(r0, r1, r2, r3, a) \
    asm volatile("ldmatrix.sync.aligned.m8n8.x4.shared.b16 {%0,%1,%2,%3}, [%4];" \
        : "=r"(r0), "=r"(r1), "=r"(r2), "=r"(r3) : "r"(a))
#define LDSM_X4_T(r0, r1, r2, r3, a) \
    asm volatile("ldmatrix.sync.aligned.m8n8.x4.trans.shared.b16 {%0,%1,%2,%3}, [%4];" \
        : "=r"(r0), "=r"(r1), "=r"(r2), "=r"(r3) : "r"(a))

__device__ __forceinline__ void mma16816(float* d, const uint32_t* a, uint32_t b0, uint32_t b1) {
    asm volatile("mma.sync.aligned.m16n8k16.row.col.f32.bf16.bf16.f32 "
        "{%0,%1,%2,%3}, {%4,%5,%6,%7}, {%8,%9}, {%0,%1,%2,%3};"
        : "+f"(d[0]), "+f"(d[1]), "+f"(d[2]), "+f"(d[3])
        : "r"(a[0]), "r"(a[1]), "r"(a[2]), "r"(a[3]), "r"(b0), "r"(b1));
}

__device__ __forceinline__ void cp16(uint32_t dst, const void* src, bool ok) {
    asm volatile("cp.async.cg.shared.global [%0], [%1], 16, %2;"
        :: "r"(dst), "l"(src), "r"(ok ? 16 : 0) : "memory");
}
#define CP_COMMIT() asm volatile("cp.async.commit_group;" ::: "memory")
#define CP_WAIT0()  asm volatile("cp.async.wait_group 0;" ::: "memory")

// ---------------- device buffers ----------------
__device__ __nv_bfloat16 g_Ahi[(size_t)HWX * C];
__device__ __nv_bfloat16 g_Alo[(size_t)HWX * C];
__device__ __nv_bfloat16 g_Bhi[(size_t)HWX * C];
__device__ __nv_bfloat16 g_Blo[(size_t)HWX * C];
__device__ __nv_bfloat16 g_whi[NL * 49 * C * C];   // [l][tap][ci][co]
__device__ __nv_bfloat16 g_wlo[NL * 49 * C * C];
__device__ float g_bf[NL * C];
__device__ float g_u[HH * C];
__device__ float g_dproj[(MAXBIN + 1) * C];
__device__ float g_weff[C + 1];

// ---------------- prep kernels ----------------
__global__ void prep_u(const float* __restrict__ x, const float* __restrict__ w_in) {
    int i = blockIdx.x, c = threadIdx.x;
    const float* xr = x + i * E;
    const float* wr = w_in + c * E;
    float s = 0.f;
    #pragma unroll 8
    for (int e = 0; e < E; e++) s += wr[e] * xr[e];
    g_u[i * C + c] = s;
}

__global__ void prep_dproj(const float* __restrict__ dist, const float* __restrict__ w_in,
                           const float* __restrict__ b_in) {
    int p = blockIdx.x, c = threadIdx.x;
    const float* dr = dist + p * E;
    const float* wr = w_in + c * E;
    float s = b_in[c];
    #pragma unroll 8
    for (int e = 0; e < E; e++) s += wr[e] * dr[e];
    g_dproj[p * C + c] = s;
}

__global__ void prep_fold(const float* __restrict__ w_dil, const float* __restrict__ gamma,
                          const float* __restrict__ var) {
    int blk = blockIdx.x;                 // l*49 + tap
    int l = blk / 49, tap = blk % 49;
    int tid = threadIdx.x;
    __nv_bfloat16* dh = g_whi + blk * 4096;
    __nv_bfloat16* dl = g_wlo + blk * 4096;
    const float* wsrc = w_dil + l * C * C * 49;
    #pragma unroll
    for (int k = 0; k < 16; k++) {
        int idx = tid * 16 + k;           // ci*64 + co
        int ci = idx >> 6, co = idx & 63;
        float s = gamma[l * C + co] * rsqrtf(var[l * C + co] + 1e-5f);
        float v = wsrc[(co * C + ci) * 49 + tap] * s;
        unsigned short h = f2bfu(v);
        dh[idx] = __ushort_as_bfloat16(h);
        dl[idx] = __float2bfloat16_rn(v - bf2f(h));
    }
}

__global__ void prep_bias(const float* __restrict__ b_dil, const float* __restrict__ gamma,
                          const float* __restrict__ beta, const float* __restrict__ mean,
                          const float* __restrict__ var) {
    int l = blockIdx.x, c = threadIdx.x;
    float s = gamma[l * C + c] * rsqrtf(var[l * C + c] + 1e-5f);
    g_bf[l * C + c] = (b_dil[l * C + c] - mean[l * C + c]) * s + beta[l * C + c];
}

__global__ void prep_weff(const float* __restrict__ w_out, const float* __restrict__ b_out,
                          const float* __restrict__ w_head, const float* __restrict__ b_head) {
    int ci = threadIdx.x;
    float s = 0.f;
    for (int co = 0; co < C; co++) s += w_head[co] * w_out[co * C + ci];
    g_weff[ci] = s;
    if (ci == 0) {
        float b = b_head[0];
        for (int co = 0; co < C; co++) b += w_head[co] * b_out[co];
        g_weff[C] = b;
    }
}

// ---------------- pair + input 1x1 conv (fp32 FFMA), writes NHWC bf16 hi/lo ----------------
__global__ void pair_gemm(const float* __restrict__ x, const float* __restrict__ w_in) {
    __shared__ float Ae[32 * 68];
    __shared__ float Be[32 * 68];
    __shared__ float xi[E];
    int i = blockIdx.y;
    int j0 = blockIdx.x * 64;
    int tid = threadIdx.x;
    xi[tid] = x[i * E + tid];
    __syncthreads();

    int ty = tid >> 4, tx = tid & 15;
    int c0 = ty * 4, p0 = tx * 4;
    int srow = tid >> 2;
    int eb = (tid & 3) * 8;
    bool jok = (j0 + srow) < WW;
    const float* xrow = x + (j0 + srow) * E;

    float acc[4][4] = {};
    #pragma unroll 1
    for (int e0 = 0; e0 < E; e0 += 32) {
        {
            const float* wr = w_in + srow * E + e0 + eb;
            #pragma unroll
            for (int k = 0; k < 8; k++) Ae[(eb + k) * 68 + srow] = wr[k] * xi[e0 + eb + k];
        }
        if (jok) {
            #pragma unroll
            for (int k = 0; k < 8; k++) Be[(eb + k) * 68 + srow] = xrow[e0 + eb + k];
        } else {
            #pragma unroll
            for (int k = 0; k < 8; k++) Be[(eb + k) * 68 + srow] = 0.f;
        }
        __syncthreads();
        #pragma unroll
        for (int e = 0; e < 32; e++) {
            float4 a4 = *(const float4*)(Ae + e * 68 + c0);
            float4 b4 = *(const float4*)(Be + e * 68 + p0);
            float av[4] = {a4.x, a4.y, a4.z, a4.w};
            float bv[4] = {b4.x, b4.y, b4.z, b4.w};
            #pragma unroll
            for (int aa = 0; aa < 4; aa++)
                #pragma unroll
                for (int bb = 0; bb < 4; bb++)
                    acc[aa][bb] = fmaf(av[aa], bv[bb], acc[aa][bb]);
        }
        __syncthreads();
    }

    #pragma unroll
    for (int bb = 0; bb < 4; bb++) {
        int j = j0 + p0 + bb;
        if (j < WW) {
            int pos = (i > j) ? (i - j) : (j - i);
            if (pos > MAXBIN) pos = MAXBIN;
            uint32_t hw[2], lw[2];
            #pragma unroll
            for (int g = 0; g < 2; g++) {
                uint32_t h2 = 0, l2 = 0;
                #pragma unroll
                for (int e = 0; e < 2; e++) {
                    int aa = g * 2 + e;
                    int c = c0 + aa;
                    float v = acc[aa][bb] + 0.5f * (g_u[i * C + c] + g_u[j * C + c]) + g_dproj[pos * C + c];
                    unsigned short h = f2bfu(v);
                    unsigned short lo = f2bfu(v - bf2f(h));
                    h2 |= ((uint32_t)h) << (16 * e);
                    l2 |= ((uint32_t)lo) << (16 * e);
                }
                hw[g] = h2; lw[g] = l2;
            }
            size_t off = ((size_t)i * WW + j) * C + c0;
            *(uint2*)(g_Ahi + off) = make_uint2(hw[0], hw[1]);
            *(uint2*)(g_Alo + off) = make_uint2(lw[0], lw[1]);
        }
    }
}

// ---------------- dilated conv: strip-reuse + cp.async + double-buffered W ----------------
// smem: bias 256 | W buf0 (hi8K+lo8K) | W buf1 | strip hi NR*128 | strip lo NR*128
#define OFF_BIAS 0
#define OFF_WB(b)  (256 + (b) * 16384)
#define OFF_STRIP  (256 + 32768)

template<int DIL>
__global__ __launch_bounds__(256, 2) void conv_strip(int l) {
    constexpr int NR = ((128 + 6 * DIL) + 31) & ~31;   // strip rows, mult of 32
    constexpr int OFF_SH = OFF_STRIP;
    constexpr int OFF_SL = OFF_STRIP + NR * 128;

    extern __shared__ char smem[];
    const uint32_t sb = smem_to_u32(smem);
    const int tid = threadIdx.x;
    const int wid = tid >> 5, lane = tid & 31;
    const int y = blockIdx.y;
    const int x0 = blockIdx.x * 128;

    const __nv_bfloat16* __restrict__ shi = (l & 1) ? g_Bhi : g_Ahi;
    const __nv_bfloat16* __restrict__ slo = (l & 1) ? g_Blo : g_Alo;
    __nv_bfloat16* __restrict__ dhi = (l & 1) ? g_Ahi : g_Bhi;
    __nv_bfloat16* __restrict__ dlo = (l & 1) ? g_Alo : g_Blo;
    const __nv_bfloat16* __restrict__ wh = g_whi + l * 49 * 4096;
    const __nv_bfloat16* __restrict__ wl = g_wlo + l * 49 * 4096;

    if (tid < C) ((float*)(smem + OFF_BIAS))[tid] = g_bf[l * C + tid];

    // W staging map: 512 chunks per component, 2 per thread
    int wCi[2]; uint32_t wSo[2], wGo[2];
    #pragma unroll
    for (int k = 0; k < 2; k++) {
        int chunk = tid + k * 256;
        wCi[k] = chunk >> 3;
        int cc = chunk & 7;
        wGo[k] = (uint32_t)(wCi[k] * 64 + cc * 8);
        wSo[k] = (uint32_t)(wCi[k] * 128 + ((cc ^ (wCi[k] & 7)) << 4));
    }

    // ldmatrix fragment address components
    const int row0 = wid * 16;
    const int quad = lane >> 3;
    const int rA = row0 + (lane & 7) + ((quad & 1) << 3);
    const int aChunkAdd = quad >> 1;
    const int rBbase = (lane & 7) + (((lane >> 3) & 1) << 3);
    const int bChunkAdd = lane >> 4;

    float acc[8][4] = {};

    #pragma unroll 1
    for (int ky = 0; ky < 7; ky++) {
        int yy = y + (ky - 3) * DIL;
        bool yok = (yy >= 0) && (yy < HH);
        size_t rowbase = (size_t)yy * WW;

        // stage strip (hi+lo) via cp.async
        #pragma unroll 1
        for (int chunk = tid; chunk < NR * 8; chunk += 256) {
            int r = chunk >> 3;
            int cc = chunk & 7;
            int xg = x0 - 3 * DIL + r;
            bool ok = yok && (xg >= 0) && (xg < WW);
            size_t g = ok ? ((rowbase + xg) * C + cc * 8) : 0;
            uint32_t so = (uint32_t)(r * 128 + ((cc ^ (r & 7)) << 4));
            cp16(sb + OFF_SH + so, shi + g, ok);
            cp16(sb + OFF_SL + so, slo + g, ok);
        }
        // stage W(ky, 0) into buf0
        {
            const __nv_bfloat16* wph = wh + (ky * 7) * 4096;
            const __nv_bfloat16* wpl = wl + (ky * 7) * 4096;
            #pragma unroll
            for (int k = 0; k < 2; k++) {
                cp16(sb + OFF_WB(0) + wSo[k],        wph + wGo[k], true);
                cp16(sb + OFF_WB(0) + 8192 + wSo[k], wpl + wGo[k], true);
            }
        }
        CP_COMMIT();
        CP_WAIT0();
        __syncthreads();

        #pragma unroll 1
        for (int kx = 0; kx < 7; kx++) {
            int buf = kx & 1;
            if (kx < 6) {
                const __nv_bfloat16* wph = wh + (ky * 7 + kx + 1) * 4096;
                const __nv_bfloat16* wpl = wl + (ky * 7 + kx + 1) * 4096;
                int nb = (kx + 1) & 1;
                #pragma unroll
                for (int k = 0; k < 2; k++) {
                    cp16(sb + OFF_WB(nb) + wSo[k],        wph + wGo[k], true);
                    cp16(sb + OFF_WB(nb) + 8192 + wSo[k], wpl + wGo[k], true);
                }
                CP_COMMIT();
            }
            const uint32_t wbh = sb + OFF_WB(buf);
            const uint32_t wbl = wbh + 8192;
            const int rowL = kx * DIL + rA;
            const uint32_t aoBase = (uint32_t)(rowL * 128);
            const int rpar = rowL & 7;

            #pragma unroll
            for (int ks = 0; ks < 4; ks++) {
                uint32_t ah[4], al[4];
                {
                    int chunk = 2 * ks + aChunkAdd;
                    uint32_t ao = aoBase + ((uint32_t)(chunk ^ rpar) << 4);
                    LDSM_X4(ah[0], ah[1], ah[2], ah[3], sb + OFF_SH + ao);
                    LDSM_X4(al[0], al[1], al[2], al[3], sb + OFF_SL + ao);
                }
                int rB = rBbase + 16 * ks;
                #pragma unroll
                for (int p = 0; p < 4; p++) {
                    int chunkB = 2 * p + bChunkAdd;
                    uint32_t bo = (uint32_t)(rB * 128 + ((chunkB ^ (rB & 7)) << 4));
                    uint32_t b0, b1, b2, b3;
                    LDSM_X4_T(b0, b1, b2, b3, wbh + bo);
                    mma16816(acc[2 * p],     ah, b0, b1);
                    mma16816(acc[2 * p + 1], ah, b2, b3);
                    mma16816(acc[2 * p],     al, b0, b1);
                    mma16816(acc[2 * p + 1], al, b2, b3);
                    LDSM_X4_T(b0, b1, b2, b3, wbl + bo);
                    mma16816(acc[2 * p],     ah, b0, b1);
                    mma16816(acc[2 * p + 1], ah, b2, b3);
                }
            }
            if (kx < 6) {
                CP_WAIT0();
                __syncthreads();
            }
        }
        __syncthreads();   // protect strip + W overwrite next ky
    }

    // epilogue: + bias + residual(hi+lo), relu, re-split, store
    const float* sbias = (const float*)(smem + OFF_BIAS);
    int rtop = row0 + (lane >> 2);
    int cpair = (lane & 3) * 2;
    #pragma unroll
    for (int half = 0; half < 2; half++) {
        int xg = x0 + rtop + half * 8;
        if (xg < WW) {
            size_t prow = ((size_t)y * WW + xg) * C;
            #pragma unroll
            for (int nt = 0; nt < 8; nt++) {
                int col = nt * 8 + cpair;
                size_t p = prow + col;
                uint32_t rh = *(const uint32_t*)(shi + p);
                uint32_t rl = *(const uint32_t*)(slo + p);
                float v0 = acc[nt][half * 2]     + sbias[col]     + bf2f(rh & 0xffffu) + bf2f(rl & 0xffffu);
                float v1 = acc[nt][half * 2 + 1] + sbias[col + 1] + bf2f(rh >> 16)     + bf2f(rl >> 16);
                v0 = fmaxf(v0, 0.f); v1 = fmaxf(v1, 0.f);
                unsigned short h0 = f2bfu(v0), h1 = f2bfu(v1);
                unsigned short l0 = f2bfu(v0 - bf2f(h0)), l1 = f2bfu(v1 - bf2f(h1));
                *(uint32_t*)(dhi + p) = (uint32_t)h0 | ((uint32_t)h1 << 16);
                *(uint32_t*)(dlo + p) = (uint32_t)l0 | ((uint32_t)l1 << 16);
            }
        }
    }
}

// ---------------- head (conv_out folded into w_eff) ----------------
__device__ __forceinline__ int tri_offs(int r) { return r * NOUT - (r * (r - 1)) / 2; }

__global__ void head_k(float* __restrict__ out) {
    int k = blockIdx.x * blockDim.x + threadIdx.x;
    if (k >= NTRI) return;
    float disc = (2.f * NOUT + 1.f) * (2.f * NOUT + 1.f) - 8.f * (float)k;
    int r = (int)(((2.f * NOUT + 1.f) - sqrtf(disc)) * 0.5f);
    if (r < 0) r = 0;
    if (r > NOUT - 1) r = NOUT - 1;
    while (r > 0 && tri_offs(r) > k) r--;
    while (r < NOUT - 1 && tri_offs(r + 1) <= k) r++;
    int c = r + (k - tri_offs(r));
    int yy = CROPV + r, xx = CROPV + c;
    size_t p = ((size_t)yy * WW + xx) * C;

    float s = g_weff[C];
    const uint4* rh = (const uint4*)(g_Bhi + p);
    const uint4* rl = (const uint4*)(g_Blo + p);
    #pragma unroll
    for (int q = 0; q < 8; q++) {
        uint4 vh = rh[q], vl = rl[q];
        uint32_t vhw[4] = {vh.x, vh.y, vh.z, vh.w};
        uint32_t vlw[4] = {vl.x, vl.y, vl.z, vl.w};
        #pragma unroll
        for (int e = 0; e < 4; e++) {
            int ci = q * 8 + e * 2;
            float h0 = bf2f(vhw[e] & 0xffffu) + bf2f(vlw[e] & 0xffffu);
            float h1 = bf2f(vhw[e] >> 16) + bf2f(vlw[e] >> 16);
            s = fmaf(h0, __ldg(&g_weff[ci]), s);
            s = fmaf(h1, __ldg(&g_weff[ci + 1]), s);
        }
    }
    out[k] = s;
}

// ------------------------------------------------------------------
template<int DIL>
static void launch_conv(int l) {
    constexpr int NR = ((128 + 6 * DIL) + 31) & ~31;
    constexpr int SMEM = 256 + 32768 + NR * 256;
    static bool done = false;
    if (!done) {
        cudaFuncSetAttribute(conv_strip<DIL>, cudaFuncAttributeMaxDynamicSharedMemorySize, SMEM);
        done = true;
    }
    conv_strip<DIL><<<dim3((WW + 127) / 128, HH), 256, SMEM>>>(l);
}

extern "C" void kernel_launch(void* const* d_in, const int* in_sizes, int n_in,
                              void* d_out, int out_size) {
    const float* x      = (const float*)d_in[0];
    const float* dist   = (const float*)d_in[1];
    const float* w_in   = (const float*)d_in[2];
    const float* b_in   = (const float*)d_in[3];
    const float* w_dil  = (const float*)d_in[4];
    const float* b_dil  = (const float*)d_in[5];
    const float* gamma  = (const float*)d_in[6];
    const float* beta   = (const float*)d_in[7];
    const float* mean   = (const float*)d_in[8];
    const float* var    = (const float*)d_in[9];
    const float* w_out  = (const float*)d_in[10];
    const float* b_out  = (const float*)d_in[11];
    const float* w_head = (const float*)d_in[12];
    const float* b_head = (const float*)d_in[13];
    float* out = (float*)d_out;

    prep_u<<<HH, C>>>(x, w_in);
    prep_dproj<<<MAXBIN + 1, C>>>(dist, w_in, b_in);
    prep_fold<<<NL * 49, 256>>>(w_dil, gamma, var);
    prep_bias<<<NL, C>>>(b_dil, gamma, beta, mean, var);
    prep_weff<<<1, C>>>(w_out, b_out, w_head, b_head);

    pair_gemm<<<dim3((WW + 63) / 64, HH), 256>>>(x, w_in);

    launch_conv<1>(0);
    launch_conv<2>(1);
    launch_conv<4>(2);
    launch_conv<8>(3);
    launch_conv<16>(4);
    launch_conv<32>(5);
    launch_conv<64>(6);

    head_k<<<(NTRI + 255) / 256, 256>>>(out);
}